// round 6
// baseline (speedup 1.0000x reference)
#include <cuda_runtime.h>
#include <cuda_fp16.h>
#include <math.h>
#include <stdint.h>

// ---------------------------------------------------------------------------
// VQ-VAE VectorQuantizer forward — fp16 HFMA2 candidate filter (provable
// per-pixel error window) + exact fp32 rescore, fused.
//   out = [ z_q_st (2097152) | vq_loss | indices (32768) | perplexity | usage (1024) ]
// ---------------------------------------------------------------------------

#define D_DIM   64
#define KCODES  1024
#define HW      1024
#define TM      128
#define KC      128
#define NCHUNK  8
#define NTILES  256
#define CAP     32

#define OFS_LOSS  2097152
#define OFS_IDX   2097153
#define OFS_PPL   2129921
#define OFS_USAGE 2129922

__device__ int   g_counts[KCODES];
__device__ float g_e2[KCODES];
__device__ float g_sse;
__device__ int   g_maxe_bits;                       // max|e| as positive-float bits
__device__ __align__(16) unsigned g_e_h[32 * KCODES];  // [d2][k] half2 codebook

// ---------------------------------------------------------------------------
// Kernel 1: prep — exact sequential e2, half2 codebook [d2][k], max|e|, zeros
// ---------------------------------------------------------------------------
__global__ void vq_prep(const float* __restrict__ cb) {
    const int k = blockIdx.x * 256 + threadIdx.x;   // grid 4 x 256 = 1024
    const float4* row = reinterpret_cast<const float4*>(cb + (size_t)k * D_DIM);
    float e2 = 0.f, ma = 0.f;
#pragma unroll
    for (int q = 0; q < 16; ++q) {
        float4 v = row[q];
        e2 = fmaf(v.x, v.x, e2); e2 = fmaf(v.y, v.y, e2);   // d-ascending seq
        e2 = fmaf(v.z, v.z, e2); e2 = fmaf(v.w, v.w, e2);
        ma = fmaxf(ma, fmaxf(fmaxf(fabsf(v.x), fabsf(v.y)),
                             fmaxf(fabsf(v.z), fabsf(v.w))));
        __half2 h0 = __floats2half2_rn(v.x, v.y);
        __half2 h1 = __floats2half2_rn(v.z, v.w);
        g_e_h[(2 * q + 0) * KCODES + k] = *reinterpret_cast<unsigned*>(&h0);
        g_e_h[(2 * q + 1) * KCODES + k] = *reinterpret_cast<unsigned*>(&h1);
    }
    g_e2[k] = e2;
#pragma unroll
    for (int o = 16; o; o >>= 1) ma = fmaxf(ma, __shfl_xor_sync(0xffffffffu, ma, o));
    if ((threadIdx.x & 31) == 0) atomicMax(&g_maxe_bits, __float_as_int(ma));
    g_counts[k] = 0;
    if (k == 0) g_sse = 0.f;
}

// ---------------------------------------------------------------------------
// Kernel 2: main — HFMA2 scores, windowed candidates, exact rescore, outputs
// ---------------------------------------------------------------------------
struct SmemVQ {
    unsigned       z_h[32][TM];        // 16384 : half2 z, [d2][px]
    unsigned       ebuf[32][KC];       // 16384 : half2 e chunk, [d2][k]
    float          e2s[KCODES];        //  4096
    unsigned       gbest_u[TM];        //   512 : bits(best_score + 16)
    float          delta_s[TM];        //   512
    int            cnt_s[TM];          //   512
    unsigned short cand_s[TM * CAP];   //  8192
    int            hist[KCODES];       //  4096
};                                     // ~50.7 KB -> 2 CTAs/SM

__global__ void __launch_bounds__(256, 2)
vq_main(const float* __restrict__ ze, const float* __restrict__ cb,
        float* __restrict__ out) {
    extern __shared__ __align__(16) char smem_raw[];
    SmemVQ* sm = reinterpret_cast<SmemVQ*>(smem_raw);

    const int tid  = threadIdx.x;
    const int tile = blockIdx.x;
    const int b    = tile >> 3;
    const int hw0  = (tile & 7) * TM;

    // ---- stage chunk 0, e2, hist ------------------------------------------
    {
        const int d2 = tid >> 3, q = tid & 7;       // 16 u32 per thread
        const uint4* src = reinterpret_cast<const uint4*>(g_e_h + d2 * KCODES + q * 16);
        uint4* dst = reinterpret_cast<uint4*>(&sm->ebuf[d2][q * 16]);
        dst[0] = src[0]; dst[1] = src[1]; dst[2] = src[2]; dst[3] = src[3];
    }
    for (int i = tid; i < KCODES; i += 256) { sm->e2s[i] = g_e2[i]; sm->hist[i] = 0; }
    __syncthreads();

    const float maxe = __int_as_float(g_maxe_bits);

    // ---- per-pixel pass: pack z to half2, bound, warm-up best -------------
    if (tid < TM) {
        const int px = tid;
        const float* zp = ze + (size_t)b * D_DIM * HW + hw0 + px;
        float l1 = 0.f;
        unsigned zw[32];
#pragma unroll
        for (int d2 = 0; d2 < 32; ++d2) {
            float v0 = zp[(2 * d2) * HW], v1 = zp[(2 * d2 + 1) * HW];
            l1 += fabsf(v0) + fabsf(v1);
            __half2 h = __floats2half2_rn(v0, v1);
            unsigned u = *reinterpret_cast<unsigned*>(&h);
            zw[d2] = u;
            sm->z_h[d2][px] = u;
        }
        const float E = maxe * l1 * 0.02f;          // rigorous f16 dot-error bound
        sm->delta_s[px] = 5.2f * E + 1e-5f;         // window > 4E superset req.
        sm->cnt_s[px]   = 0;

        // warm-up: best of 16 codes seeds the shared threshold
        const int k0 = (px & 7) * 16;
        float tb = 1e30f;
#pragma unroll 2
        for (int q = 0; q < 16; ++q) {
            __half2 acc = __float2half2_rn(0.f);
#pragma unroll
            for (int d2 = 0; d2 < 32; ++d2) {
                __half2 zz = *reinterpret_cast<const __half2*>(&zw[d2]);
                __half2 ee = *reinterpret_cast<const __half2*>(&sm->ebuf[d2][k0 + q]);
                acc = __hfma2(zz, ee, acc);
            }
            float2 f = __half22float2(acc);
            tb = fminf(tb, fmaf(-2.f, f.x + f.y, sm->e2s[k0 + q]));
        }
        sm->gbest_u[px] = __float_as_uint(tb + 16.0f);
    }
    __syncthreads();

    // ---- main loop: 128 px x 1024 codes, thread tile 8 px x 8 codes -------
    const int pcol = tid & 15, krow = tid >> 4;
    const int p0 = pcol * 8, kloc0 = krow * 8;
    const int d2_st = tid >> 3, q_st = tid & 7;

    for (int c = 0; c < NCHUNK; ++c) {
        if (c) {   // stage chunk c (codebook f16 is L2-hot: 128 KB x 296 CTAs)
            const uint4* src = reinterpret_cast<const uint4*>(
                g_e_h + d2_st * KCODES + c * KC + q_st * 16);
            uint4* dst = reinterpret_cast<uint4*>(&sm->ebuf[d2_st][q_st * 16]);
            dst[0] = src[0]; dst[1] = src[1]; dst[2] = src[2]; dst[3] = src[3];
            __syncthreads();
        }
        const int kb = c * KC;

        __half2 acc[8][8];
#pragma unroll
        for (int j = 0; j < 8; ++j)
#pragma unroll
            for (int kk = 0; kk < 8; ++kk) acc[j][kk] = __float2half2_rn(0.f);

#pragma unroll 4
        for (int d2 = 0; d2 < 32; ++d2) {
            uint4 zA = *reinterpret_cast<const uint4*>(&sm->z_h[d2][p0]);
            uint4 zB = *reinterpret_cast<const uint4*>(&sm->z_h[d2][p0 + 4]);
            uint4 eA = *reinterpret_cast<const uint4*>(&sm->ebuf[d2][kloc0]);
            uint4 eB = *reinterpret_cast<const uint4*>(&sm->ebuf[d2][kloc0 + 4]);
            const __half2 zz[8] = {
                *reinterpret_cast<__half2*>(&zA.x), *reinterpret_cast<__half2*>(&zA.y),
                *reinterpret_cast<__half2*>(&zA.z), *reinterpret_cast<__half2*>(&zA.w),
                *reinterpret_cast<__half2*>(&zB.x), *reinterpret_cast<__half2*>(&zB.y),
                *reinterpret_cast<__half2*>(&zB.z), *reinterpret_cast<__half2*>(&zB.w)};
            const __half2 ee[8] = {
                *reinterpret_cast<__half2*>(&eA.x), *reinterpret_cast<__half2*>(&eA.y),
                *reinterpret_cast<__half2*>(&eA.z), *reinterpret_cast<__half2*>(&eA.w),
                *reinterpret_cast<__half2*>(&eB.x), *reinterpret_cast<__half2*>(&eB.y),
                *reinterpret_cast<__half2*>(&eB.z), *reinterpret_cast<__half2*>(&eB.w)};
#pragma unroll
            for (int j = 0; j < 8; ++j)
#pragma unroll
                for (int kk = 0; kk < 8; ++kk)
                    acc[j][kk] = __hfma2(zz[j], ee[kk], acc[j][kk]);
        }

        // epilogue: scores vs chunk-start shared best (provable superset)
        float thv[8], dlt[8], tcur[8];
#pragma unroll
        for (int j = 0; j < 8; ++j) {
            dlt[j]  = sm->delta_s[p0 + j];
            thv[j]  = __uint_as_float(sm->gbest_u[p0 + j]) - 16.0f + dlt[j];
            tcur[j] = 1e30f;
        }
#pragma unroll
        for (int kk = 0; kk < 8; ++kk) {
            const int k = kb + kloc0 + kk;
            const float e2k = sm->e2s[k];
#pragma unroll
            for (int j = 0; j < 8; ++j) {
                float2 f = __half22float2(acc[j][kk]);
                float s = fmaf(-2.f, f.x + f.y, e2k);
                tcur[j] = fminf(tcur[j], s);
                if (s <= thv[j]) {
                    int pos = atomicAdd(&sm->cnt_s[p0 + j], 1);
                    if (pos < CAP) sm->cand_s[(p0 + j) * CAP + pos] = (unsigned short)k;
                }
            }
        }
#pragma unroll
        for (int j = 0; j < 8; ++j)
            atomicMin(&sm->gbest_u[p0 + j], __float_as_uint(tcur[j] + 16.0f));
        __syncthreads();
    }

    // ---- exact rescore (reference-identical rounding), outputs ------------
    if (tid < TM) {
        const int px = tid;
        const float* zp = ze + (size_t)b * D_DIM * HW + hw0 + px;
        float z[D_DIM];
#pragma unroll
        for (int d = 0; d < D_DIM; ++d) z[d] = zp[d * HW];
        float z2 = 0.f;
#pragma unroll
        for (int d = 0; d < D_DIM; ++d) z2 = fmaf(z[d], z[d], z2);

        const int n = sm->cnt_s[px];
        int bi = 0x7fffffff;
        float bd = 3.4e38f;
        if (n <= CAP) {
            for (int i = 0; i < n; ++i) {
                const int k = sm->cand_s[px * CAP + i];
                const float4* er = reinterpret_cast<const float4*>(cb + (size_t)k * D_DIM);
                float dot = 0.f;
#pragma unroll
                for (int q = 0; q < 16; ++q) {
                    float4 v = er[q];
                    dot = fmaf(z[q * 4 + 0], v.x, dot);
                    dot = fmaf(z[q * 4 + 1], v.y, dot);
                    dot = fmaf(z[q * 4 + 2], v.z, dot);
                    dot = fmaf(z[q * 4 + 3], v.w, dot);
                }
                float dist = fmaf(-2.f, dot, z2 + sm->e2s[k]);
                if (dist < bd || (dist == bd && k < bi)) { bd = dist; bi = k; }
            }
        } else {  // overflow: exact full scan (correctness insurance)
            for (int k = 0; k < KCODES; ++k) {
                const float4* er = reinterpret_cast<const float4*>(cb + (size_t)k * D_DIM);
                float dot = 0.f;
#pragma unroll
                for (int q = 0; q < 16; ++q) {
                    float4 v = er[q];
                    dot = fmaf(z[q * 4 + 0], v.x, dot);
                    dot = fmaf(z[q * 4 + 1], v.y, dot);
                    dot = fmaf(z[q * 4 + 2], v.z, dot);
                    dot = fmaf(z[q * 4 + 3], v.w, dot);
                }
                float dist = fmaf(-2.f, dot, z2 + sm->e2s[k]);
                if (dist < bd) { bd = dist; bi = k; }
            }
        }

        out[OFS_IDX + tile * TM + px] = (float)bi;
        atomicAdd(&sm->hist[bi], 1);

        // z_q_st with reference's two roundings + SSE
        const float4* er = reinterpret_cast<const float4*>(cb + (size_t)bi * D_DIM);
        float* zo = out + (size_t)b * D_DIM * HW + hw0 + px;
        float sse = 0.f;
#pragma unroll
        for (int q = 0; q < 16; ++q) {
            float4 v = er[q];
            float vv[4] = {v.x, v.y, v.z, v.w};
#pragma unroll
            for (int cc = 0; cc < 4; ++cc) {
                int d = q * 4 + cc;
                float diff = vv[cc] - z[d];      // fl(z_q - z_e)
                sse = fmaf(diff, diff, sse);
                zo[d * HW] = z[d] + diff;        // fl(z_e + fl(z_q - z_e))
            }
        }
#pragma unroll
        for (int o = 16; o; o >>= 1) sse += __shfl_xor_sync(0xffffffffu, sse, o);
        if ((tid & 31) == 0) atomicAdd(&g_sse, sse);
    }
    __syncthreads();

    for (int i = tid; i < KCODES; i += 256) {
        int cnum = sm->hist[i];
        if (cnum) atomicAdd(&g_counts[i], cnum);
    }
}

// ---------------------------------------------------------------------------
// Kernel 3: finalize — usage, perplexity, vq_loss
// ---------------------------------------------------------------------------
__global__ void vq_final(float* __restrict__ out) {
    __shared__ float red[32];
    int t = threadIdx.x;
    float u = (float)g_counts[t] / 32768.0f;
    out[OFS_USAGE + t] = u;
    float h = u * logf(u + 1e-10f);
#pragma unroll
    for (int o = 16; o; o >>= 1) h += __shfl_xor_sync(0xffffffffu, h, o);
    if ((t & 31) == 0) red[t >> 5] = h;
    __syncthreads();
    if (t < 32) {
        float v = red[t];
#pragma unroll
        for (int o = 16; o; o >>= 1) v += __shfl_xor_sync(0xffffffffu, v, o);
        if (t == 0) {
            out[OFS_PPL] = expf(-v);
            float m = g_sse / 2097152.0f;
            out[OFS_LOSS] = m + 0.25f * m;
        }
    }
}

// ---------------------------------------------------------------------------
extern "C" void kernel_launch(void* const* d_in, const int* in_sizes, int n_in,
                              void* d_out, int out_size) {
    const float* a0 = (const float*)d_in[0];
    const float* a1 = (const float*)d_in[1];
    const float* ze = a0;
    const float* cb = a1;
    if (n_in >= 2 && in_sizes[0] == KCODES * D_DIM) { ze = a1; cb = a0; }
    float* out = (float*)d_out;

    static_assert(sizeof(SmemVQ) <= 100 * 1024, "smem too big");
    cudaFuncSetAttribute(vq_main, cudaFuncAttributeMaxDynamicSharedMemorySize,
                         (int)sizeof(SmemVQ));

    vq_prep<<<4, 256>>>(cb);
    vq_main<<<NTILES, 256, sizeof(SmemVQ)>>>(ze, cb, out);
    vq_final<<<1, 1024>>>(out);
}

// round 8
// speedup vs baseline: 4.7319x; 4.7319x over previous
#include <cuda_runtime.h>
#include <math.h>
#include <stdint.h>

// ---------------------------------------------------------------------------
// VQ-VAE VectorQuantizer forward — exact fp32 via packed f32x2 FMA.
// (Toolchain evidence: tcgen05 rejected by base sm_100 ptxas; mma.sync /
//  dp4a / HFMA2 paths all run 3-6x below native rate here. FFMA2 is the
//  fastest proven engine; this round trims prep + staging overheads.)
//   out = [ z_q_st (2097152) | vq_loss | indices (32768) | perplexity | usage (1024) ]
// ---------------------------------------------------------------------------

#define D_DIM   64
#define KCODES  1024
#define HW      1024
#define TM      128          // pixels per CTA tile
#define KC      128          // codes per chunk
#define NCHUNK  (KCODES / KC)
#define NTILES  256

#define OFS_LOSS  2097152
#define OFS_IDX   2097153
#define OFS_PPL   2129921
#define OFS_USAGE 2129922

__device__ int   g_counts[KCODES];
__device__ float g_e2[KCODES];
__device__ float g_sse;

// ---- packed f32x2 helpers --------------------------------------------------
__device__ __forceinline__ unsigned long long pack2(float x, float y) {
    unsigned long long r;
    asm("mov.b64 %0, {%1, %2};" : "=l"(r) : "f"(x), "f"(y));
    return r;
}
__device__ __forceinline__ void fma2(unsigned long long& d,
                                     unsigned long long a,
                                     unsigned long long b) {
    asm("fma.rn.f32x2 %0, %1, %2, %0;" : "+l"(d) : "l"(a), "l"(b));
}
__device__ __forceinline__ float2 unpack2(unsigned long long v) {
    float2 f;
    asm("mov.b64 {%0, %1}, %2;" : "=f"(f.x), "=f"(f.y) : "l"(v));
    return f;
}

// ---------------------------------------------------------------------------
// Kernel 1: prep — exact sequential e2 (one code/thread), zero accumulators
// ---------------------------------------------------------------------------
__global__ void vq_prep(const float* __restrict__ cb) {
    const int k = blockIdx.x * 128 + threadIdx.x;   // grid 8 x 128 = 1024
    const float4* row = reinterpret_cast<const float4*>(cb + (size_t)k * D_DIM);
    float s = 0.f;
#pragma unroll
    for (int q = 0; q < 16; ++q) {                  // d-ascending sequential fmaf
        float4 v = row[q];
        s = fmaf(v.x, v.x, s); s = fmaf(v.y, v.y, s);
        s = fmaf(v.z, v.z, s); s = fmaf(v.w, v.w, s);
    }
    g_e2[k] = s;
    g_counts[k] = 0;
    if (k == 0) g_sse = 0.f;
}

// ---------------------------------------------------------------------------
// Kernel 2: main — f32x2 distances, argmin, z_q gather, transposed store, stats
//   grid 256, 256 thr, 2 CTAs/SM. Thread tile: 8 px x 8 codes (code-pair pack).
// ---------------------------------------------------------------------------
struct SmemLayout {
    float z_s[D_DIM][TM + 4];     // z tile, [d][p]
    float e_s[D_DIM][KC + 4];     // codebook chunk, [d][k]; reused as z_q staging
    float z2_s[TM];
    float e2s[KCODES];
    float red_d[8][TM];
    int   red_i[8][TM];
    int   idx_s[TM];
    int   cnt_s[KCODES];
};

__global__ void __launch_bounds__(256, 2)
vq_main(const float* __restrict__ ze, const float* __restrict__ cb,
        float* __restrict__ out) {
    extern __shared__ __align__(16) char smem_raw[];
    SmemLayout* sm = reinterpret_cast<SmemLayout*>(smem_raw);

    const int tid  = threadIdx.x;
    const int tile = blockIdx.x;
    const int b    = tile >> 3;            // 8 tiles per batch image
    const int hw0  = (tile & 7) * TM;
    const float* zbase = ze + (size_t)b * D_DIM * HW + hw0;

    // zero histogram, load e2
    for (int i = tid; i < KCODES; i += 256) sm->cnt_s[i] = 0;
    for (int i = tid; i < KCODES; i += 256) sm->e2s[i] = g_e2[i];

    // load z tile (coalesced over hw)
    for (int f = tid; f < D_DIM * TM; f += 256) {
        int d = f >> 7, p = f & 127;
        sm->z_s[d][p] = zbase[d * HW + p];
    }
    __syncthreads();

    // per-pixel squared norm, sequential fmaf (reference rounding)
    if (tid < TM) {
        float s = 0.f;
#pragma unroll
        for (int d = 0; d < D_DIM; ++d) s = fmaf(sm->z_s[d][tid], sm->z_s[d][tid], s);
        sm->z2_s[tid] = s;
    }
    __syncthreads();

    const int pcol  = tid & 15;
    const int krow  = tid >> 4;
    const int p0    = pcol * 8;
    const int kloc0 = krow * 8;

    float z2r[8];
#pragma unroll
    for (int j = 0; j < 8; ++j) z2r[j] = sm->z2_s[p0 + j];

    float bestd[8];
    int   besti[8];
#pragma unroll
    for (int j = 0; j < 8; ++j) { bestd[j] = 3.4e38f; besti[j] = 0; }

    const int k_st = tid & 127;            // staging: warp writes one d-row,
    const int h_st = tid >> 7;             // 32 consecutive k -> conflict-free STS

    for (int c = 0; c < NCHUNK; ++c) {
        const int kb = c * KC;
        if (c) __syncthreads();            // previous chunk's e_s reads done

        // ---- stage codebook chunk, transposed to [d][k] (conflict-free) ----
        {
            const float4* src = reinterpret_cast<const float4*>(
                                    cb + (size_t)(kb + k_st) * D_DIM) + h_st * 8;
#pragma unroll
            for (int i = 0; i < 8; ++i) {
                float4 v = src[i];
                int d0 = h_st * 32 + i * 4;
                sm->e_s[d0 + 0][k_st] = v.x;
                sm->e_s[d0 + 1][k_st] = v.y;
                sm->e_s[d0 + 2][k_st] = v.z;
                sm->e_s[d0 + 3][k_st] = v.w;
            }
        }
        __syncthreads();

        // ---- accumulate dot products: 8 px x 8 codes, packed over code pairs
        unsigned long long acc[8][4];
#pragma unroll
        for (int j = 0; j < 8; ++j)
#pragma unroll
            for (int kk = 0; kk < 4; ++kk) acc[j][kk] = 0ull;

#pragma unroll 16
        for (int d = 0; d < D_DIM; ++d) {
            ulonglong2 eA = *reinterpret_cast<const ulonglong2*>(&sm->e_s[d][kloc0]);
            ulonglong2 eB = *reinterpret_cast<const ulonglong2*>(&sm->e_s[d][kloc0 + 4]);
            float4 za = *reinterpret_cast<const float4*>(&sm->z_s[d][p0]);
            float4 zb = *reinterpret_cast<const float4*>(&sm->z_s[d][p0 + 4]);
            float zr[8] = {za.x, za.y, za.z, za.w, zb.x, zb.y, zb.z, zb.w};
#pragma unroll
            for (int j = 0; j < 8; ++j) {
                unsigned long long zz = pack2(zr[j], zr[j]);
                fma2(acc[j][0], zz, eA.x);
                fma2(acc[j][1], zz, eA.y);
                fma2(acc[j][2], zz, eB.x);
                fma2(acc[j][3], zz, eB.y);
            }
        }

        // ---- epilogue: exact reference rounding, strict-< keeps first min --
        float e2r[8];
#pragma unroll
        for (int kk = 0; kk < 8; ++kk) e2r[kk] = sm->e2s[kb + kloc0 + kk];

#pragma unroll
        for (int j = 0; j < 8; ++j) {
            float a = z2r[j];
#pragma unroll
            for (int kk = 0; kk < 4; ++kk) {
                float2 s = unpack2(acc[j][kk]);
                float d0 = fmaf(-2.f, s.x, a + e2r[kk * 2]);
                float d1 = fmaf(-2.f, s.y, a + e2r[kk * 2 + 1]);
                int k0 = kb + kloc0 + kk * 2;
                if (d0 < bestd[j]) { bestd[j] = d0; besti[j] = k0; }
                if (d1 < bestd[j]) { bestd[j] = d1; besti[j] = k0 + 1; }
            }
        }
    }

    // ---- cross-thread argmin: lexicographic (dist, index) min over 16 krows
#pragma unroll
    for (int j = 0; j < 8; ++j) {
        float od = __shfl_xor_sync(0xffffffffu, bestd[j], 16);
        int   oi = __shfl_xor_sync(0xffffffffu, besti[j], 16);
        if (od < bestd[j] || (od == bestd[j] && oi < besti[j])) {
            bestd[j] = od; besti[j] = oi;
        }
    }
    const int w = tid >> 5;
    if ((tid & 16) == 0) {
#pragma unroll
        for (int j = 0; j < 8; ++j) {
            sm->red_d[w][p0 + j] = bestd[j];
            sm->red_i[w][p0 + j] = besti[j];
        }
    }
    __syncthreads();

    if (tid < TM) {
        float bd = sm->red_d[0][tid];
        int   bi = sm->red_i[0][tid];
#pragma unroll
        for (int w2 = 1; w2 < 8; ++w2) {
            float d2 = sm->red_d[w2][tid];
            int   i2 = sm->red_i[w2][tid];
            if (d2 < bd || (d2 == bd && i2 < bi)) { bd = d2; bi = i2; }
        }
        sm->idx_s[tid] = bi;
        out[OFS_IDX + tile * TM + tid] = (float)bi;
        atomicAdd(&sm->cnt_s[bi], 1);
    }
    __syncthreads();

    // flush histogram
    for (int i = tid; i < KCODES; i += 256) {
        int cnum = sm->cnt_s[i];
        if (cnum) atomicAdd(&g_counts[i], cnum);
    }

    // ---- gather z_q, build z_q_st with reference rounding, SSE; stage in e_s
    {
        int p = tid >> 1, h = tid & 1;
        int ci = sm->idx_s[p];
        const float4* crow = reinterpret_cast<const float4*>(
                                 cb + (size_t)ci * D_DIM) + h * 8;
        float ssel = 0.f;
#pragma unroll
        for (int i = 0; i < 8; ++i) {
            float4 v = crow[i];
            int d0 = h * 32 + i * 4;
            float vv[4] = {v.x, v.y, v.z, v.w};
#pragma unroll
            for (int cc = 0; cc < 4; ++cc) {
                int d = d0 + cc;
                float zev  = sm->z_s[d][p];
                float diff = vv[cc] - zev;           // fl(z_q - z_e)
                ssel = fmaf(diff, diff, ssel);
                sm->e_s[d][p] = zev + diff;          // fl(z_e + fl(z_q - z_e))
            }
        }
#pragma unroll
        for (int o = 16; o; o >>= 1) ssel += __shfl_xor_sync(0xffffffffu, ssel, o);
        if ((tid & 31) == 0) atomicAdd(&g_sse, ssel);
    }
    __syncthreads();

    // ---- write z_q_st, coalesced over hw ----
    float* zo = out + (size_t)b * D_DIM * HW + hw0;
    for (int f = tid; f < D_DIM * TM; f += 256) {
        int d = f >> 7, p = f & 127;
        zo[d * HW + p] = sm->e_s[d][p];
    }
}

// ---------------------------------------------------------------------------
// Kernel 3: finalize — usage, perplexity, vq_loss
// ---------------------------------------------------------------------------
__global__ void vq_final(float* __restrict__ out) {
    __shared__ float red[32];
    int t = threadIdx.x;
    float u = (float)g_counts[t] / 32768.0f;
    out[OFS_USAGE + t] = u;
    float h = u * logf(u + 1e-10f);
#pragma unroll
    for (int o = 16; o; o >>= 1) h += __shfl_xor_sync(0xffffffffu, h, o);
    if ((t & 31) == 0) red[t >> 5] = h;
    __syncthreads();
    if (t < 32) {
        float v = red[t];
#pragma unroll
        for (int o = 16; o; o >>= 1) v += __shfl_xor_sync(0xffffffffu, v, o);
        if (t == 0) {
            out[OFS_PPL] = expf(-v);
            float m = g_sse / 2097152.0f;
            out[OFS_LOSS] = m + 0.25f * m;
        }
    }
}

// ---------------------------------------------------------------------------
extern "C" void kernel_launch(void* const* d_in, const int* in_sizes, int n_in,
                              void* d_out, int out_size) {
    const float* a0 = (const float*)d_in[0];
    const float* a1 = (const float*)d_in[1];
    const float* ze = a0;
    const float* cb = a1;
    if (n_in >= 2 && in_sizes[0] == KCODES * D_DIM) { ze = a1; cb = a0; }
    float* out = (float*)d_out;

    static_assert(sizeof(SmemLayout) < 100 * 1024, "smem layout too big");
    cudaFuncSetAttribute(vq_main, cudaFuncAttributeMaxDynamicSharedMemorySize,
                         (int)sizeof(SmemLayout));

    vq_prep<<<8, 128>>>(cb);
    vq_main<<<NTILES, 256, sizeof(SmemLayout)>>>(ze, cb, out);
    vq_final<<<1, 1024>>>(out);
}